// round 8
// baseline (speedup 1.0000x reference)
#include <cuda_runtime.h>
#include <cuda_fp16.h>
#include <math.h>
#include <stdint.h>

#define HID 128
#define TILE_E 64
#define THREADS 256
#define NPB 32
#define N_NODES_MAX 100000

__device__ __half g_hsrc[N_NODES_MAX * HID];   // node_emb @ W1[0:128]
__device__ __half g_htgt[N_NODES_MAX * HID];   // node_emb @ W1[128:256]
__device__ __half g_w2h[4 * 4096];             // W2 chunks, fragment-major
__device__ float  g_wx[2][16 * 128];
__device__ float  g_wp[2][3 * 128];
__device__ float  g_cb[2][128];

__device__ __forceinline__ float silu(float v) {
    return __fdividef(v, 1.0f + __expf(-v));
}
__device__ __forceinline__ void mma16(float4& d, uint32_t a0, uint32_t a1,
                                      uint32_t a2, uint32_t a3,
                                      uint32_t b0, uint32_t b1) {
    asm volatile(
        "mma.sync.aligned.m16n8k16.row.col.f32.f16.f16.f32 "
        "{%0,%1,%2,%3},{%4,%5,%6,%7},{%8,%9},{%0,%1,%2,%3};"
        : "+f"(d.x), "+f"(d.y), "+f"(d.z), "+f"(d.w)
        : "r"(a0), "r"(a1), "r"(a2), "r"(a3), "r"(b0), "r"(b1));
}
__device__ __forceinline__ void ldm4(uint32_t& a0, uint32_t& a1,
                                     uint32_t& a2, uint32_t& a3, uint32_t addr) {
    asm volatile("ldmatrix.sync.aligned.m8n8.x4.shared.b16 {%0,%1,%2,%3},[%4];"
                 : "=r"(a0), "=r"(a1), "=r"(a2), "=r"(a3) : "r"(addr));
}
// swizzled 16B-chunk position within a 256B row (16 chunks)
__device__ __forceinline__ int sw_pos(int row, int cc) {
    return (cc & 8) + ((cc & 7) ^ (row & 7));
}

// ------------- Kernel 1: weight products ------------------------------------
__global__ void weight_prod(const float* __restrict__ Wa,
                            const float* __restrict__ ba,
                            const float* __restrict__ Wp,
                            const float* __restrict__ bp,
                            const float* __restrict__ W1) {
    __shared__ float swa[16 * 128];
    __shared__ float swp[3 * 128];
    __shared__ float sb[128];
    int p = blockIdx.x;
    int j = threadIdx.x;
    for (int i = j; i < 16 * 128; i += 128) swa[i] = Wa[i];
    for (int i = j; i < 3 * 128; i += 128) swp[i] = Wp[i];
    sb[j] = ba[j] + bp[j];
    __syncthreads();

    float ax[16];
#pragma unroll
    for (int i = 0; i < 16; i++) ax[i] = 0.f;
    float ap[3] = {0.f, 0.f, 0.f};
    float ac = 0.f;
    for (int k = 0; k < 128; k++) {
        float w = W1[(p * 128 + k) * 128 + j];
#pragma unroll
        for (int i = 0; i < 16; i++) ax[i] += swa[i * 128 + k] * w;
#pragma unroll
        for (int i = 0; i < 3; i++) ap[i] += swp[i * 128 + k] * w;
        ac += sb[k] * w;
    }
#pragma unroll
    for (int i = 0; i < 16; i++) g_wx[p][i * 128 + j] = ax[i];
#pragma unroll
    for (int i = 0; i < 3; i++) g_wp[p][i * 128 + j] = ap[i];
    g_cb[p][j] = ac;
}

// ------------- Kernel 2: per-node h_src / h_tgt ------------------------------
__global__ void node_h_kernel(const float* __restrict__ x,
                              const float* __restrict__ pos, int N) {
    int j = threadIdx.x;
    float wx0[16], wx1[16], wp0[3], wp1[3];
#pragma unroll
    for (int i = 0; i < 16; i++) {
        wx0[i] = g_wx[0][i * 128 + j];
        wx1[i] = g_wx[1][i * 128 + j];
    }
#pragma unroll
    for (int i = 0; i < 3; i++) {
        wp0[i] = g_wp[0][i * 128 + j];
        wp1[i] = g_wp[1][i * 128 + j];
    }
    float c0 = g_cb[0][j], c1 = g_cb[1][j];

    __shared__ float xs[NPB][16];
    __shared__ float ps[NPB][3];
    int n0 = blockIdx.x * NPB;
    for (int i = j; i < NPB * 16; i += 128) {
        int n = n0 + (i >> 4);
        xs[i >> 4][i & 15] = (n < N) ? x[n * 16 + (i & 15)] : 0.0f;
    }
    for (int i = j; i < NPB * 3; i += 128) {
        int n = n0 + i / 3;
        ps[i / 3][i % 3] = (n < N) ? pos[n * 3 + i % 3] : 0.0f;
    }
    __syncthreads();
    for (int n = 0; n < NPB; n++) {
        if (n0 + n >= N) break;
        float s0 = c0, s1 = c1;
#pragma unroll
        for (int i = 0; i < 16; i++) {
            s0 += xs[n][i] * wx0[i];
            s1 += xs[n][i] * wx1[i];
        }
#pragma unroll
        for (int i = 0; i < 3; i++) {
            s0 += ps[n][i] * wp0[i];
            s1 += ps[n][i] * wp1[i];
        }
        g_hsrc[(n0 + n) * HID + j] = __float2half(s0);
        g_htgt[(n0 + n) * HID + j] = __float2half(s1);
    }
}

// ------------- Kernel 3: W2 fragment-major packing ---------------------------
__global__ void prep_w2(const float* __restrict__ W2) {
    int c = blockIdx.x;
    __half* dst = g_w2h + c * 4096;
    for (int idx = threadIdx.x; idx < 4096; idx += 256) {
        int u = idx & 3;
        int t = (idx >> 2) & 3;
        int n = (idx >> 4) & 127;
        int step = idx >> 11;
        int kl = step * 16 + ((u >> 1) << 3) + 2 * t + (u & 1);
        dst[idx] = __float2half(W2[(c * 32 + kl) * 128 + n]);
    }
}

// ------------- Kernel 4: persistent pipelined edge MLP ----------------------
__global__ void __launch_bounds__(THREADS, 2)
edge_mlp3(const float* __restrict__ pos, const int* __restrict__ ei,
          const float* __restrict__ W1, const float* __restrict__ b1,
          const float* __restrict__ b2,
          const float* __restrict__ W3, const float* __restrict__ b3,
          float* __restrict__ out, int E, int ntiles) {
    extern __shared__ __align__(16) char smc[];
    __half* rawS = (__half*)smc;                   // 16384 B
    __half* rawT = (__half*)(smc + 16384);         // 16384 B
    __half* hs   = (__half*)(smc + 32768);         // 16384 B
    __half* W2f  = (__half*)(smc + 49152);         // 32768 B
    float*  part = (float*)(smc + 81920);          // 4096 B
    float*  aux  = (float*)(smc + 86016);
    int*   soff = (int*)aux;            // [2][64]
    int*   doff = (int*)(aux + 128);    // [2][64]
    float* dist = aux + 256;            // [2][64]
    float* w256 = aux + 384;            // 128
    float* sb1  = aux + 512;            // 128
    float* sb2  = aux + 640;            // 128
    float* w3s  = aux + 768;            // 512
    float* b3s  = aux + 1280;           // 4

    const uint32_t rawSu = (uint32_t)__cvta_generic_to_shared(rawS);
    const uint32_t rawTu = (uint32_t)__cvta_generic_to_shared(rawT);
    const uint32_t hsu   = (uint32_t)__cvta_generic_to_shared(hs);

    const int tid  = threadIdx.x;
    const int lane = tid & 31;
    const int wid  = tid >> 5;
    const int m_base = (wid >> 2) * 32;
    const int n_warp = (wid & 3) * 32;
    const int g = lane >> 2;
    const int t = lane & 3;

    // ---- resident tables (once per block) ----
    {
        const uint4* s4 = (const uint4*)g_w2h;
        uint4* d4 = (uint4*)W2f;
#pragma unroll
        for (int i = 0; i < 8; i++) d4[tid + 256 * i] = s4[tid + 256 * i];
    }
    if (tid < 128) {
        w256[tid] = W1[256 * 128 + tid];
        sb1[tid] = b1[tid];
        sb2[tid] = b2[tid];
    }
    for (int i = tid; i < 512; i += THREADS) w3s[i] = W3[i];
    if (tid < 4) b3s[tid] = b3[tid];

    auto load_idx = [&](int tile, int b) {   // tid < 64 only
        int ge = tile * TILE_E + tid;
        if (ge >= E) ge = E - 1;
        int s = ei[ge], d = ei[E + ge];
        soff[b * 64 + tid] = s * HID;
        doff[b * 64 + tid] = d * HID;
        float dx = pos[s * 3 + 0] - pos[d * 3 + 0];
        float dy = pos[s * 3 + 1] - pos[d * 3 + 1];
        float dz = pos[s * 3 + 2] - pos[d * 3 + 2];
        dist[b * 64 + tid] = sqrtf(dx * dx + dy * dy + dz * dz);
    };
    auto issue_gather = [&](int b) {         // all threads, 8 cp.async each
        int grow = (tid >> 1) & 63;
        int gt = tid >> 7;
        int gh = tid & 1;
        const __half* base = gt ? (g_htgt + doff[b * 64 + grow])
                                : (g_hsrc + soff[b * 64 + grow]);
        uint32_t drow = (gt ? rawTu : rawSu) + grow * 256;
#pragma unroll
        for (int i = 0; i < 8; i++) {
            int c = gh * 8 + i;
            uint32_t dst = drow + (uint32_t)(sw_pos(grow, c) << 4);
            asm volatile("cp.async.cg.shared.global [%0],[%1],16;"
                         :: "r"(dst), "l"(base + c * 8) : "memory");
        }
    };

    // ---- prologue ----
    if (tid < 64 && blockIdx.x < ntiles) load_idx(blockIdx.x, 0);
    __syncthreads();
    if (blockIdx.x < ntiles) issue_gather(0);
    asm volatile("cp.async.commit_group;" ::: "memory");

    int buf = 0;
#pragma unroll 1
    for (int tile = blockIdx.x; tile < ntiles; tile += gridDim.x, buf ^= 1) {
        asm volatile("cp.async.wait_group 0;" ::: "memory");
        __syncthreads();

        // ---- conv: hs = fp16(silu(raw_src + raw_tgt + dist*w256 + b1)) ----
        {
            int crow = tid >> 2, cq = tid & 3;
            float dd = dist[buf * 64 + crow];
            char* rs = (char*)rawS + crow * 256;
            char* rt = (char*)rawT + crow * 256;
            char* hb = (char*)hs + crow * 256;
#pragma unroll
            for (int i = 0; i < 4; i++) {
                int c = cq + 4 * i;
                int p16 = sw_pos(crow, c) << 4;
                uint4 av = *(const uint4*)(rs + p16);
                uint4 bv = *(const uint4*)(rt + p16);
                int c0 = c * 8;
                float4 wA = *(const float4*)&w256[c0];
                float4 wB = *(const float4*)&w256[c0 + 4];
                float4 bA = *(const float4*)&sb1[c0];
                float4 bB = *(const float4*)&sb1[c0 + 4];
                const __half2* ah = (const __half2*)&av;
                const __half2* bh = (const __half2*)&bv;
                float2 f0 = __half22float2(ah[0]), g0 = __half22float2(bh[0]);
                float2 f1 = __half22float2(ah[1]), g1 = __half22float2(bh[1]);
                float2 f2 = __half22float2(ah[2]), g2 = __half22float2(bh[2]);
                float2 f3 = __half22float2(ah[3]), g3 = __half22float2(bh[3]);
                __half2 o0 = __floats2half2_rn(silu(f0.x + g0.x + dd * wA.x + bA.x),
                                               silu(f0.y + g0.y + dd * wA.y + bA.y));
                __half2 o1 = __floats2half2_rn(silu(f1.x + g1.x + dd * wA.z + bA.z),
                                               silu(f1.y + g1.y + dd * wA.w + bA.w));
                __half2 o2 = __floats2half2_rn(silu(f2.x + g2.x + dd * wB.x + bB.x),
                                               silu(f2.y + g2.y + dd * wB.y + bB.y));
                __half2 o3 = __floats2half2_rn(silu(f3.x + g3.x + dd * wB.z + bB.z),
                                               silu(f3.y + g3.y + dd * wB.w + bB.w));
                uint4 ov;
                ov.x = *(uint32_t*)&o0; ov.y = *(uint32_t*)&o1;
                ov.z = *(uint32_t*)&o2; ov.w = *(uint32_t*)&o3;
                *(uint4*)(hb + p16) = ov;
            }
        }
        int ntile = tile + gridDim.x;
        if (tid < 64 && ntile < ntiles) load_idx(ntile, buf ^ 1);
        __syncthreads();   // hs ready; raw consumed; next idx ready

        if (ntile < ntiles) issue_gather(buf ^ 1);
        asm volatile("cp.async.commit_group;" ::: "memory");

        // ---- GEMM2: h1 @ W2 (K=128), warp tile 32x32 ----
        float4 acc[2][4];
#pragma unroll
        for (int i = 0; i < 2; i++)
#pragma unroll
            for (int j = 0; j < 4; j++) acc[i][j] = make_float4(0.f, 0.f, 0.f, 0.f);
#pragma unroll
        for (int c = 0; c < 4; c++) {
            const __half* Bp = W2f + c * 4096;
#pragma unroll
            for (int s = 0; s < 2; s++) {
                int sg = c * 2 + s;
                uint2 bf[4];
#pragma unroll
                for (int ni = 0; ni < 4; ni++) {
                    int n = n_warp + ni * 8 + g;
                    bf[ni] = *(const uint2*)(Bp + (((s * 128 + n) << 2) + t) * 4);
                }
#pragma unroll
                for (int mi = 0; mi < 2; mi++) {
                    int lrow = m_base + mi * 16 + (lane & 7) + (lane & 8);
                    int cc = sg * 2 + (lane >> 4);
                    uint32_t addr = hsu + lrow * 256 + (sw_pos(lrow, cc) << 4);
                    uint32_t a0, a1, a2, a3;
                    ldm4(a0, a1, a2, a3, addr);
#pragma unroll
                    for (int ni = 0; ni < 4; ni++)
                        mma16(acc[mi][ni], a0, a1, a2, a3, bf[ni].x, bf[ni].y);
                }
            }
        }

        // ---- epilogue: silu(D2+b2), GEMM3 dot, shfl reduce over quad -------
#pragma unroll
        for (int mi = 0; mi < 2; mi++) {
            float4 plo = make_float4(0.f, 0.f, 0.f, 0.f);
            float4 phi = make_float4(0.f, 0.f, 0.f, 0.f);
#pragma unroll
            for (int ni = 0; ni < 4; ni++) {
                int c0 = n_warp + ni * 8 + 2 * t;
                float4 a = acc[mi][ni];
                float v0 = silu(a.x + sb2[c0]);
                float v1 = silu(a.y + sb2[c0 + 1]);
                float v2 = silu(a.z + sb2[c0]);
                float v3 = silu(a.w + sb2[c0 + 1]);
                float4 w0 = *(const float4*)&w3s[c0 * 4];
                float4 w1 = *(const float4*)&w3s[(c0 + 1) * 4];
                plo.x += v0 * w0.x + v1 * w1.x;
                plo.y += v0 * w0.y + v1 * w1.y;
                plo.z += v0 * w0.z + v1 * w1.z;
                plo.w += v0 * w0.w + v1 * w1.w;
                phi.x += v2 * w0.x + v3 * w1.x;
                phi.y += v2 * w0.y + v3 * w1.y;
                phi.z += v2 * w0.z + v3 * w1.z;
                phi.w += v2 * w0.w + v3 * w1.w;
            }
#pragma unroll
            for (int m = 1; m <= 2; m <<= 1) {
                plo.x += __shfl_xor_sync(0xffffffffu, plo.x, m);
                plo.y += __shfl_xor_sync(0xffffffffu, plo.y, m);
                plo.z += __shfl_xor_sync(0xffffffffu, plo.z, m);
                plo.w += __shfl_xor_sync(0xffffffffu, plo.w, m);
                phi.x += __shfl_xor_sync(0xffffffffu, phi.x, m);
                phi.y += __shfl_xor_sync(0xffffffffu, phi.y, m);
                phi.z += __shfl_xor_sync(0xffffffffu, phi.z, m);
                phi.w += __shfl_xor_sync(0xffffffffu, phi.w, m);
            }
            if (t == 0) {
                int r = m_base + mi * 16 + g;
                *(float4*)&part[((wid & 3) * 64 + r) * 4] = plo;
                *(float4*)&part[((wid & 3) * 64 + r + 8) * 4] = phi;
            }
        }
        __syncthreads();

        if (tid < 64) {
            int ge = tile * TILE_E + tid;
            float4 o = make_float4(b3s[0], b3s[1], b3s[2], b3s[3]);
#pragma unroll
            for (int ng = 0; ng < 4; ng++) {
                float4 pv = *(const float4*)&part[(ng * 64 + tid) * 4];
                o.x += pv.x; o.y += pv.y; o.z += pv.z; o.w += pv.w;
            }
            if (ge < E) *(float4*)&out[ge * 4] = o;
        }
    }
}

// ---------------------------------------------------------------------------
extern "C" void kernel_launch(void* const* d_in, const int* in_sizes, int n_in,
                              void* d_out, int out_size) {
    const float* x   = (const float*)d_in[0];
    const float* pos = (const float*)d_in[1];
    const int*   ei  = (const int*)  d_in[2];
    const float* Wa  = (const float*)d_in[3];
    const float* ba  = (const float*)d_in[4];
    const float* Wp  = (const float*)d_in[5];
    const float* bp  = (const float*)d_in[6];
    const float* W1  = (const float*)d_in[7];
    const float* b1  = (const float*)d_in[8];
    const float* W2  = (const float*)d_in[9];
    const float* b2  = (const float*)d_in[10];
    const float* W3  = (const float*)d_in[11];
    const float* b3  = (const float*)d_in[12];
    float* out = (float*)d_out;

    int N = in_sizes[0] / 16;
    int E = in_sizes[2] / 2;
    int ntiles = (E + TILE_E - 1) / TILE_E;

    // smem: raw 32768 + hs 16384 + W2f 32768 + part 4096 + aux 5136 = 91152 B
    size_t smem_bytes = 91152;
    cudaFuncSetAttribute(edge_mlp3,
                         cudaFuncAttributeMaxDynamicSharedMemorySize,
                         (int)smem_bytes);

    weight_prod<<<2, 128>>>(Wa, ba, Wp, bp, W1);
    prep_w2<<<4, 256>>>(W2);
    node_h_kernel<<<(N + NPB - 1) / NPB, 128>>>(x, pos, N);

    int grid = 2 * 148;
    if (grid > ntiles) grid = ntiles;
    edge_mlp3<<<grid, THREADS, smem_bytes>>>(
        pos, ei, W1, b1, b2, W3, b3, out, E, ntiles);
}

// round 9
// speedup vs baseline: 1.0289x; 1.0289x over previous
#include <cuda_runtime.h>
#include <cuda_fp16.h>
#include <math.h>
#include <stdint.h>

#define HID 128
#define BM  64
#define THREADS 256
#define NPB 32
#define N_NODES_MAX 100000

__device__ __half g_hsrc[N_NODES_MAX * HID];   // node_emb @ W1[0:128]
__device__ __half g_htgt[N_NODES_MAX * HID];   // node_emb @ W1[128:256]
__device__ __half g_w2h[4 * 4096];             // W2 chunks, fragment-major
__device__ float  g_wx[2][16 * 128];
__device__ float  g_wp[2][3 * 128];
__device__ float  g_cb[2][128];

// fast silu: v * sigmoid(v) = 0.5v(1 + tanh(v/2)); 1 MUFU + 2 FMA
__device__ __forceinline__ float silu(float v) {
    float th;
    asm("tanh.approx.f32 %0, %1;" : "=f"(th) : "f"(v * 0.5f));
    return fmaf(0.5f * v, th, 0.5f * v);
}
__device__ __forceinline__ void mma16(float4& d, uint32_t a0, uint32_t a1,
                                      uint32_t a2, uint32_t a3,
                                      uint32_t b0, uint32_t b1) {
    asm volatile(
        "mma.sync.aligned.m16n8k16.row.col.f32.f16.f16.f32 "
        "{%0,%1,%2,%3},{%4,%5,%6,%7},{%8,%9},{%0,%1,%2,%3};"
        : "+f"(d.x), "+f"(d.y), "+f"(d.z), "+f"(d.w)
        : "r"(a0), "r"(a1), "r"(a2), "r"(a3), "r"(b0), "r"(b1));
}
__device__ __forceinline__ void ldm4(uint32_t& a0, uint32_t& a1,
                                     uint32_t& a2, uint32_t& a3, uint32_t addr) {
    asm volatile("ldmatrix.sync.aligned.m8n8.x4.shared.b16 {%0,%1,%2,%3},[%4];"
                 : "=r"(a0), "=r"(a1), "=r"(a2), "=r"(a3) : "r"(addr));
}
// swizzled 16B-chunk position within a 256B row (16 chunks)
__device__ __forceinline__ int sw_pos(int row, int cc) {
    return (cc & 8) + ((cc & 7) ^ (row & 7));
}

// ------------- Kernel 1: weight products ------------------------------------
__global__ void weight_prod(const float* __restrict__ Wa,
                            const float* __restrict__ ba,
                            const float* __restrict__ Wp,
                            const float* __restrict__ bp,
                            const float* __restrict__ W1) {
    __shared__ float swa[16 * 128];
    __shared__ float swp[3 * 128];
    __shared__ float sb[128];
    int p = blockIdx.x;
    int j = threadIdx.x;
    for (int i = j; i < 16 * 128; i += 128) swa[i] = Wa[i];
    for (int i = j; i < 3 * 128; i += 128) swp[i] = Wp[i];
    sb[j] = ba[j] + bp[j];
    __syncthreads();

    float ax[16];
#pragma unroll
    for (int i = 0; i < 16; i++) ax[i] = 0.f;
    float ap[3] = {0.f, 0.f, 0.f};
    float ac = 0.f;
    for (int k = 0; k < 128; k++) {
        float w = W1[(p * 128 + k) * 128 + j];
#pragma unroll
        for (int i = 0; i < 16; i++) ax[i] += swa[i * 128 + k] * w;
#pragma unroll
        for (int i = 0; i < 3; i++) ap[i] += swp[i * 128 + k] * w;
        ac += sb[k] * w;
    }
#pragma unroll
    for (int i = 0; i < 16; i++) g_wx[p][i * 128 + j] = ax[i];
#pragma unroll
    for (int i = 0; i < 3; i++) g_wp[p][i * 128 + j] = ap[i];
    g_cb[p][j] = ac;
}

// ------------- Kernel 2: per-node h_src / h_tgt ------------------------------
__global__ void node_h_kernel(const float* __restrict__ x,
                              const float* __restrict__ pos, int N) {
    int j = threadIdx.x;
    float wx0[16], wx1[16], wp0[3], wp1[3];
#pragma unroll
    for (int i = 0; i < 16; i++) {
        wx0[i] = g_wx[0][i * 128 + j];
        wx1[i] = g_wx[1][i * 128 + j];
    }
#pragma unroll
    for (int i = 0; i < 3; i++) {
        wp0[i] = g_wp[0][i * 128 + j];
        wp1[i] = g_wp[1][i * 128 + j];
    }
    float c0 = g_cb[0][j], c1 = g_cb[1][j];

    __shared__ float xs[NPB][16];
    __shared__ float ps[NPB][3];
    int n0 = blockIdx.x * NPB;
    for (int i = j; i < NPB * 16; i += 128) {
        int n = n0 + (i >> 4);
        xs[i >> 4][i & 15] = (n < N) ? x[n * 16 + (i & 15)] : 0.0f;
    }
    for (int i = j; i < NPB * 3; i += 128) {
        int n = n0 + i / 3;
        ps[i / 3][i % 3] = (n < N) ? pos[n * 3 + i % 3] : 0.0f;
    }
    __syncthreads();
    for (int n = 0; n < NPB; n++) {
        if (n0 + n >= N) break;
        float s0 = c0, s1 = c1;
#pragma unroll
        for (int i = 0; i < 16; i++) {
            s0 += xs[n][i] * wx0[i];
            s1 += xs[n][i] * wx1[i];
        }
#pragma unroll
        for (int i = 0; i < 3; i++) {
            s0 += ps[n][i] * wp0[i];
            s1 += ps[n][i] * wp1[i];
        }
        g_hsrc[(n0 + n) * HID + j] = __float2half(s0);
        g_htgt[(n0 + n) * HID + j] = __float2half(s1);
    }
}

// ------------- Kernel 3: W2 fragment-major packing ---------------------------
__global__ void prep_w2(const float* __restrict__ W2) {
    int c = blockIdx.x;
    __half* dst = g_w2h + c * 4096;
    for (int idx = threadIdx.x; idx < 4096; idx += 256) {
        int u = idx & 3;
        int t = (idx >> 2) & 3;
        int n = (idx >> 4) & 127;
        int step = idx >> 11;
        int kl = step * 16 + ((u >> 1) << 3) + 2 * t + (u & 1);
        dst[idx] = __float2half(W2[(c * 32 + kl) * 128 + n]);
    }
}

// ------------- Kernel 4: edge MLP (small tiles, high occupancy) -------------
__global__ void __launch_bounds__(THREADS, 4)
edge_mlp4(const float* __restrict__ pos, const int* __restrict__ ei,
          const float* __restrict__ W1, const float* __restrict__ b1,
          const float* __restrict__ b2,
          const float* __restrict__ W3, const float* __restrict__ b3,
          float* __restrict__ out, int E) {
    __shared__ __align__(16) __half hs[BM * HID];        // 16 KB, swizzled
    __shared__ __align__(16) float part[4 * BM * 4];     // 4 KB
    __shared__ float w256[128], sb1[128], sb2[128], w3s[512], b3s[4];

    const uint32_t hsu = (uint32_t)__cvta_generic_to_shared(hs);
    const int tid  = threadIdx.x;
    const int lane = tid & 31;
    const int wid  = tid >> 5;
    const int m_base = (wid >> 2) * 32;
    const int n_warp = (wid & 3) * 32;
    const int g = lane >> 2;
    const int t = lane & 3;
    const int tile0 = blockIdx.x * BM;

    // ---- load weight tables ----
    if (tid < 128) {
        w256[tid] = W1[256 * 128 + tid];
        sb1[tid] = b1[tid];
        sb2[tid] = b2[tid];
    } else {
        int i = tid - 128;
        w3s[i] = W3[i];
        w3s[i + 128] = W3[i + 128];
        w3s[i + 256] = W3[i + 256];
        w3s[i + 384] = W3[i + 384];
        if (i < 4) b3s[i] = b3[i];
    }
    __syncthreads();

    // ---- conv: h1 = fp16(silu(hsrc + htgt + dist*w256 + b1)) -> hs ---------
    {
        const int row = tid >> 2;           // 0..63
        const int q   = tid & 3;            // quarter of the 128 cols
        int ge = tile0 + row; if (ge >= E) ge = E - 1;
        int s = ei[ge], d = ei[E + ge];
        float dx = pos[s * 3 + 0] - pos[d * 3 + 0];
        float dy = pos[s * 3 + 1] - pos[d * 3 + 1];
        float dz = pos[s * 3 + 2] - pos[d * 3 + 2];
        float dd = sqrtf(dx * dx + dy * dy + dz * dz);
        const __half* ps_ = g_hsrc + s * HID + q * 32;
        const __half* pt_ = g_htgt + d * HID + q * 32;
        char* hb = (char*)hs + row * 256;
#pragma unroll
        for (int i = 0; i < 4; i++) {
            uint4 av = *(const uint4*)(ps_ + i * 8);
            uint4 bv = *(const uint4*)(pt_ + i * 8);
            int cc = q * 4 + i;
            int c0 = cc * 8;
            float4 wA = *(const float4*)&w256[c0];
            float4 wB = *(const float4*)&w256[c0 + 4];
            float4 bA = *(const float4*)&sb1[c0];
            float4 bB = *(const float4*)&sb1[c0 + 4];
            const __half2* ah = (const __half2*)&av;
            const __half2* bh = (const __half2*)&bv;
            float2 f0 = __half22float2(ah[0]), g0 = __half22float2(bh[0]);
            float2 f1 = __half22float2(ah[1]), g1 = __half22float2(bh[1]);
            float2 f2 = __half22float2(ah[2]), g2 = __half22float2(bh[2]);
            float2 f3 = __half22float2(ah[3]), g3 = __half22float2(bh[3]);
            __half2 o0 = __floats2half2_rn(silu(f0.x + g0.x + dd * wA.x + bA.x),
                                           silu(f0.y + g0.y + dd * wA.y + bA.y));
            __half2 o1 = __floats2half2_rn(silu(f1.x + g1.x + dd * wA.z + bA.z),
                                           silu(f1.y + g1.y + dd * wA.w + bA.w));
            __half2 o2 = __floats2half2_rn(silu(f2.x + g2.x + dd * wB.x + bB.x),
                                           silu(f2.y + g2.y + dd * wB.y + bB.y));
            __half2 o3 = __floats2half2_rn(silu(f3.x + g3.x + dd * wB.z + bB.z),
                                           silu(f3.y + g3.y + dd * wB.w + bB.w));
            uint4 ov;
            ov.x = *(uint32_t*)&o0; ov.y = *(uint32_t*)&o1;
            ov.z = *(uint32_t*)&o2; ov.w = *(uint32_t*)&o3;
            *(uint4*)(hb + (sw_pos(row, cc) << 4)) = ov;
        }
    }
    __syncthreads();

    // ---- GEMM2: h1 @ W2 (K=128), warp tile 32x32, B-frags from global ------
    float4 acc[2][4];
#pragma unroll
    for (int i = 0; i < 2; i++)
#pragma unroll
        for (int j = 0; j < 4; j++) acc[i][j] = make_float4(0.f, 0.f, 0.f, 0.f);
#pragma unroll
    for (int c = 0; c < 4; c++) {
        const __half* Bp = g_w2h + c * 4096;
#pragma unroll
        for (int s = 0; s < 2; s++) {
            int sg = c * 2 + s;
            uint2 bf[4];
#pragma unroll
            for (int ni = 0; ni < 4; ni++) {
                int n = n_warp + ni * 8 + g;
                bf[ni] = *(const uint2*)(Bp + (((s * 128 + n) << 2) + t) * 4);
            }
#pragma unroll
            for (int mi = 0; mi < 2; mi++) {
                int lrow = m_base + mi * 16 + (lane & 7) + (lane & 8);
                int cc = sg * 2 + (lane >> 4);
                uint32_t addr = hsu + lrow * 256 + (sw_pos(lrow, cc) << 4);
                uint32_t a0, a1, a2, a3;
                ldm4(a0, a1, a2, a3, addr);
#pragma unroll
                for (int ni = 0; ni < 4; ni++)
                    mma16(acc[mi][ni], a0, a1, a2, a3, bf[ni].x, bf[ni].y);
            }
        }
    }

    // ---- epilogue: silu(D2+b2), GEMM3 dot, shfl reduce over quad -----------
#pragma unroll
    for (int mi = 0; mi < 2; mi++) {
        float4 plo = make_float4(0.f, 0.f, 0.f, 0.f);
        float4 phi = make_float4(0.f, 0.f, 0.f, 0.f);
#pragma unroll
        for (int ni = 0; ni < 4; ni++) {
            int c0 = n_warp + ni * 8 + 2 * t;
            float4 a = acc[mi][ni];
            float v0 = silu(a.x + sb2[c0]);
            float v1 = silu(a.y + sb2[c0 + 1]);
            float v2 = silu(a.z + sb2[c0]);
            float v3 = silu(a.w + sb2[c0 + 1]);
            float4 w0 = *(const float4*)&w3s[c0 * 4];
            float4 w1 = *(const float4*)&w3s[(c0 + 1) * 4];
            plo.x += v0 * w0.x + v1 * w1.x;
            plo.y += v0 * w0.y + v1 * w1.y;
            plo.z += v0 * w0.z + v1 * w1.z;
            plo.w += v0 * w0.w + v1 * w1.w;
            phi.x += v2 * w0.x + v3 * w1.x;
            phi.y += v2 * w0.y + v3 * w1.y;
            phi.z += v2 * w0.z + v3 * w1.z;
            phi.w += v2 * w0.w + v3 * w1.w;
        }
#pragma unroll
        for (int m = 1; m <= 2; m <<= 1) {
            plo.x += __shfl_xor_sync(0xffffffffu, plo.x, m);
            plo.y += __shfl_xor_sync(0xffffffffu, plo.y, m);
            plo.z += __shfl_xor_sync(0xffffffffu, plo.z, m);
            plo.w += __shfl_xor_sync(0xffffffffu, plo.w, m);
            phi.x += __shfl_xor_sync(0xffffffffu, phi.x, m);
            phi.y += __shfl_xor_sync(0xffffffffu, phi.y, m);
            phi.z += __shfl_xor_sync(0xffffffffu, phi.z, m);
            phi.w += __shfl_xor_sync(0xffffffffu, phi.w, m);
        }
        if (t == 0) {
            int r = m_base + mi * 16 + g;
            *(float4*)&part[((wid & 3) * BM + r) * 4] = plo;
            *(float4*)&part[((wid & 3) * BM + r + 8) * 4] = phi;
        }
    }
    __syncthreads();

    if (tid < BM) {
        int ge = tile0 + tid;
        float4 o = make_float4(b3s[0], b3s[1], b3s[2], b3s[3]);
#pragma unroll
        for (int ng = 0; ng < 4; ng++) {
            float4 pv = *(const float4*)&part[(ng * BM + tid) * 4];
            o.x += pv.x; o.y += pv.y; o.z += pv.z; o.w += pv.w;
        }
        if (ge < E) *(float4*)&out[ge * 4] = o;
    }
}

// ---------------------------------------------------------------------------
extern "C" void kernel_launch(void* const* d_in, const int* in_sizes, int n_in,
                              void* d_out, int out_size) {
    const float* x   = (const float*)d_in[0];
    const float* pos = (const float*)d_in[1];
    const int*   ei  = (const int*)  d_in[2];
    const float* Wa  = (const float*)d_in[3];
    const float* ba  = (const float*)d_in[4];
    const float* Wp  = (const float*)d_in[5];
    const float* bp  = (const float*)d_in[6];
    const float* W1  = (const float*)d_in[7];
    const float* b1  = (const float*)d_in[8];
    const float* W2  = (const float*)d_in[9];
    const float* b2  = (const float*)d_in[10];
    const float* W3  = (const float*)d_in[11];
    const float* b3  = (const float*)d_in[12];
    float* out = (float*)d_out;

    int N = in_sizes[0] / 16;
    int E = in_sizes[2] / 2;

    weight_prod<<<2, 128>>>(Wa, ba, Wp, bp, W1);
    prep_w2<<<4, 256>>>(W2);
    node_h_kernel<<<(N + NPB - 1) / NPB, 128>>>(x, pos, N);
    edge_mlp4<<<(E + BM - 1) / BM, THREADS>>>(
        pos, ei, W1, b1, b2, W3, b3, out, E);
}

// round 10
// speedup vs baseline: 1.5492x; 1.5056x over previous
#include <cuda_runtime.h>
#include <cuda_fp16.h>
#include <math.h>
#include <stdint.h>

#define HID 128
#define BM  128
#define THREADS 256
#define NPB 32
#define N_NODES_MAX 100000

__device__ __half g_hsrc[N_NODES_MAX * HID];   // node_emb @ W1[0:128]
__device__ __half g_htgt[N_NODES_MAX * HID];   // node_emb @ W1[128:256]
__device__ __half g_w2h[4 * 4096];             // W2 chunks, fragment-major
__device__ float  g_wx[2][16 * 128];
__device__ float  g_wp[2][3 * 128];
__device__ float  g_cb[2][128];

// fast silu: v * sigmoid(v) = 0.5v(1 + tanh(v/2))
__device__ __forceinline__ float silu(float v) {
    float th;
    asm("tanh.approx.f32 %0, %1;" : "=f"(th) : "f"(v * 0.5f));
    return fmaf(0.5f * v, th, 0.5f * v);
}
__device__ __forceinline__ void mma16(float4& d, uint32_t a0, uint32_t a1,
                                      uint32_t a2, uint32_t a3,
                                      uint32_t b0, uint32_t b1) {
    asm volatile(
        "mma.sync.aligned.m16n8k16.row.col.f32.f16.f16.f32 "
        "{%0,%1,%2,%3},{%4,%5,%6,%7},{%8,%9},{%0,%1,%2,%3};"
        : "+f"(d.x), "+f"(d.y), "+f"(d.z), "+f"(d.w)
        : "r"(a0), "r"(a1), "r"(a2), "r"(a3), "r"(b0), "r"(b1));
}
__device__ __forceinline__ void ldm4(uint32_t& a0, uint32_t& a1,
                                     uint32_t& a2, uint32_t& a3, uint32_t addr) {
    asm volatile("ldmatrix.sync.aligned.m8n8.x4.shared.b16 {%0,%1,%2,%3},[%4];"
                 : "=r"(a0), "=r"(a1), "=r"(a2), "=r"(a3) : "r"(addr));
}
// swizzled 16B-chunk position within a 256B row (stays inside its 128B half)
__device__ __forceinline__ int sw_pos(int row, int cc) {
    return (cc & 8) + ((cc & 7) ^ (row & 7));
}

// ------------- Kernel 1: weight products ------------------------------------
__global__ void weight_prod(const float* __restrict__ Wa,
                            const float* __restrict__ ba,
                            const float* __restrict__ Wp,
                            const float* __restrict__ bp,
                            const float* __restrict__ W1) {
    __shared__ float swa[16 * 128];
    __shared__ float swp[3 * 128];
    __shared__ float sb[128];
    int p = blockIdx.x;
    int j = threadIdx.x;
    for (int i = j; i < 16 * 128; i += 128) swa[i] = Wa[i];
    for (int i = j; i < 3 * 128; i += 128) swp[i] = Wp[i];
    sb[j] = ba[j] + bp[j];
    __syncthreads();

    float ax[16];
#pragma unroll
    for (int i = 0; i < 16; i++) ax[i] = 0.f;
    float ap[3] = {0.f, 0.f, 0.f};
    float ac = 0.f;
    for (int k = 0; k < 128; k++) {
        float w = W1[(p * 128 + k) * 128 + j];
#pragma unroll
        for (int i = 0; i < 16; i++) ax[i] += swa[i * 128 + k] * w;
#pragma unroll
        for (int i = 0; i < 3; i++) ap[i] += swp[i * 128 + k] * w;
        ac += sb[k] * w;
    }
#pragma unroll
    for (int i = 0; i < 16; i++) g_wx[p][i * 128 + j] = ax[i];
#pragma unroll
    for (int i = 0; i < 3; i++) g_wp[p][i * 128 + j] = ap[i];
    g_cb[p][j] = ac;
}

// ------------- Kernel 2: per-node h_src / h_tgt ------------------------------
__global__ void node_h_kernel(const float* __restrict__ x,
                              const float* __restrict__ pos, int N) {
    int j = threadIdx.x;
    float wx0[16], wx1[16], wp0[3], wp1[3];
#pragma unroll
    for (int i = 0; i < 16; i++) {
        wx0[i] = g_wx[0][i * 128 + j];
        wx1[i] = g_wx[1][i * 128 + j];
    }
#pragma unroll
    for (int i = 0; i < 3; i++) {
        wp0[i] = g_wp[0][i * 128 + j];
        wp1[i] = g_wp[1][i * 128 + j];
    }
    float c0 = g_cb[0][j], c1 = g_cb[1][j];

    __shared__ float xs[NPB][16];
    __shared__ float ps[NPB][3];
    int n0 = blockIdx.x * NPB;
    for (int i = j; i < NPB * 16; i += 128) {
        int n = n0 + (i >> 4);
        xs[i >> 4][i & 15] = (n < N) ? x[n * 16 + (i & 15)] : 0.0f;
    }
    for (int i = j; i < NPB * 3; i += 128) {
        int n = n0 + i / 3;
        ps[i / 3][i % 3] = (n < N) ? pos[n * 3 + i % 3] : 0.0f;
    }
    __syncthreads();
    for (int n = 0; n < NPB; n++) {
        if (n0 + n >= N) break;
        float s0 = c0, s1 = c1;
#pragma unroll
        for (int i = 0; i < 16; i++) {
            s0 += xs[n][i] * wx0[i];
            s1 += xs[n][i] * wx1[i];
        }
#pragma unroll
        for (int i = 0; i < 3; i++) {
            s0 += ps[n][i] * wp0[i];
            s1 += ps[n][i] * wp1[i];
        }
        g_hsrc[(n0 + n) * HID + j] = __float2half(s0);
        g_htgt[(n0 + n) * HID + j] = __float2half(s1);
    }
}

// ------------- Kernel 3: W2 fragment-major packing ---------------------------
__global__ void prep_w2(const float* __restrict__ W2) {
    int c = blockIdx.x;
    __half* dst = g_w2h + c * 4096;
    for (int idx = threadIdx.x; idx < 4096; idx += 256) {
        int u = idx & 3;
        int t = (idx >> 2) & 3;
        int n = (idx >> 4) & 127;
        int step = idx >> 11;
        int kl = step * 16 + ((u >> 1) << 3) + 2 * t + (u & 1);
        dst[idx] = __float2half(W2[(c * 32 + kl) * 128 + n]);
    }
}

// ------------- Kernel 4: edge MLP (coalesced gather, 32x64 warp tiles) ------
__global__ void __launch_bounds__(THREADS, 2)
edge_mlp5(const float* __restrict__ pos, const int* __restrict__ ei,
          const float* __restrict__ W1, const float* __restrict__ b1,
          const float* __restrict__ b2,
          const float* __restrict__ W3, const float* __restrict__ b3,
          float* __restrict__ out, int E) {
    __shared__ __align__(16) __half hs[BM * HID];        // 32 KB, swizzled
    __shared__ __align__(16) float part[2 * BM * 4];     // 4 KB
    __shared__ int   soff[BM], doff[BM];
    __shared__ float dist[BM];
    __shared__ float w256[128], sb1[128], sb2[128], w3s[512], b3s[4];

    const uint32_t hsu = (uint32_t)__cvta_generic_to_shared(hs);
    const int tid  = threadIdx.x;
    const int lane = tid & 31;
    const int wid  = tid >> 5;
    const int m_base = (wid >> 1) * 32;      // 4 m-groups of 32 rows
    const int n_warp = (wid & 1) * 64;       // 2 n-groups of 64 cols
    const int g = lane >> 2;
    const int t = lane & 3;
    const int tile0 = blockIdx.x * BM;

    // ---- setup ----
    if (tid < BM) {
        int ge = tile0 + tid; if (ge >= E) ge = E - 1;
        int s = ei[ge], d = ei[E + ge];
        soff[tid] = s * HID;
        doff[tid] = d * HID;
        float dx = pos[s * 3 + 0] - pos[d * 3 + 0];
        float dy = pos[s * 3 + 1] - pos[d * 3 + 1];
        float dz = pos[s * 3 + 2] - pos[d * 3 + 2];
        dist[tid] = sqrtf(dx * dx + dy * dy + dz * dz);
    } else {
        int c = tid - BM;
        w256[c] = W1[256 * 128 + c];
        sb1[c] = b1[c];
        sb2[c] = b2[c];
    }
    for (int i = tid; i < 512; i += THREADS) w3s[i] = W3[i];
    if (tid < 4) b3s[tid] = b3[tid];
    __syncthreads();

    // ---- conv: coalesced gather + silu -> hs -------------------------------
    // per warp: 16 rows; per instr: 4 rows x one 128B half-line (8 lanes each)
    {
        const int g2 = lane >> 3;            // row within quad
        const int sub = lane & 7;            // 16B chunk within half-line
        const int rbase = wid * 16;
#pragma unroll
        for (int it = 0; it < 8; it++) {
            int half = it & 1;
            int rq = it >> 1;                // 0..3
            int row = rbase + rq * 4 + g2;
            const __half* aps = g_hsrc + soff[row] + half * 64 + sub * 8;
            const __half* apt = g_htgt + doff[row] + half * 64 + sub * 8;
            uint4 av = *(const uint4*)aps;
            uint4 bv = *(const uint4*)apt;
            float dd = dist[row];
            int cc = half * 8 + sub;
            int c0 = cc * 8;
            float4 wA = *(const float4*)&w256[c0];
            float4 wB = *(const float4*)&w256[c0 + 4];
            float4 bA = *(const float4*)&sb1[c0];
            float4 bB = *(const float4*)&sb1[c0 + 4];
            const __half2* ah = (const __half2*)&av;
            const __half2* bh = (const __half2*)&bv;
            float2 f0 = __half22float2(ah[0]), g0 = __half22float2(bh[0]);
            float2 f1 = __half22float2(ah[1]), g1 = __half22float2(bh[1]);
            float2 f2 = __half22float2(ah[2]), g2f = __half22float2(bh[2]);
            float2 f3 = __half22float2(ah[3]), g3 = __half22float2(bh[3]);
            __half2 o0 = __floats2half2_rn(silu(f0.x + g0.x + dd * wA.x + bA.x),
                                           silu(f0.y + g0.y + dd * wA.y + bA.y));
            __half2 o1 = __floats2half2_rn(silu(f1.x + g1.x + dd * wA.z + bA.z),
                                           silu(f1.y + g1.y + dd * wA.w + bA.w));
            __half2 o2 = __floats2half2_rn(silu(f2.x + g2f.x + dd * wB.x + bB.x),
                                           silu(f2.y + g2f.y + dd * wB.y + bB.y));
            __half2 o3 = __floats2half2_rn(silu(f3.x + g3.x + dd * wB.z + bB.z),
                                           silu(f3.y + g3.y + dd * wB.w + bB.w));
            uint4 ov;
            ov.x = *(uint32_t*)&o0; ov.y = *(uint32_t*)&o1;
            ov.z = *(uint32_t*)&o2; ov.w = *(uint32_t*)&o3;
            *(uint4*)((char*)hs + row * 256 + (sw_pos(row, cc) << 4)) = ov;
        }
    }
    __syncthreads();

    // ---- GEMM2: h1 @ W2 (K=128), warp tile 32x64, B-frags from global ------
    float4 acc[2][8];
#pragma unroll
    for (int i = 0; i < 2; i++)
#pragma unroll
        for (int j = 0; j < 8; j++) acc[i][j] = make_float4(0.f, 0.f, 0.f, 0.f);
#pragma unroll
    for (int c = 0; c < 4; c++) {
        const __half* Bp = g_w2h + c * 4096;
#pragma unroll
        for (int s = 0; s < 2; s++) {
            int sg = c * 2 + s;
            uint2 bf[8];
#pragma unroll
            for (int ni = 0; ni < 8; ni++) {
                int n = n_warp + ni * 8 + g;
                bf[ni] = *(const uint2*)(Bp + (((s * 128 + n) << 2) + t) * 4);
            }
#pragma unroll
            for (int mi = 0; mi < 2; mi++) {
                int lrow = m_base + mi * 16 + (lane & 7) + (lane & 8);
                int cc = sg * 2 + (lane >> 4);
                uint32_t addr = hsu + lrow * 256 + (sw_pos(lrow, cc) << 4);
                uint32_t a0, a1, a2, a3;
                ldm4(a0, a1, a2, a3, addr);
#pragma unroll
                for (int ni = 0; ni < 8; ni++)
                    mma16(acc[mi][ni], a0, a1, a2, a3, bf[ni].x, bf[ni].y);
            }
        }
    }

    // ---- epilogue: silu(D2+b2), GEMM3 dot, shfl reduce over quad -----------
#pragma unroll
    for (int mi = 0; mi < 2; mi++) {
        float4 plo = make_float4(0.f, 0.f, 0.f, 0.f);
        float4 phi = make_float4(0.f, 0.f, 0.f, 0.f);
#pragma unroll
        for (int ni = 0; ni < 8; ni++) {
            int c0 = n_warp + ni * 8 + 2 * t;
            float4 a = acc[mi][ni];
            float v0 = silu(a.x + sb2[c0]);
            float v1 = silu(a.y + sb2[c0 + 1]);
            float v2 = silu(a.z + sb2[c0]);
            float v3 = silu(a.w + sb2[c0 + 1]);
            float4 w0 = *(const float4*)&w3s[c0 * 4];
            float4 w1 = *(const float4*)&w3s[(c0 + 1) * 4];
            plo.x += v0 * w0.x + v1 * w1.x;
            plo.y += v0 * w0.y + v1 * w1.y;
            plo.z += v0 * w0.z + v1 * w1.z;
            plo.w += v0 * w0.w + v1 * w1.w;
            phi.x += v2 * w0.x + v3 * w1.x;
            phi.y += v2 * w0.y + v3 * w1.y;
            phi.z += v2 * w0.z + v3 * w1.z;
            phi.w += v2 * w0.w + v3 * w1.w;
        }
#pragma unroll
        for (int m = 1; m <= 2; m <<= 1) {
            plo.x += __shfl_xor_sync(0xffffffffu, plo.x, m);
            plo.y += __shfl_xor_sync(0xffffffffu, plo.y, m);
            plo.z += __shfl_xor_sync(0xffffffffu, plo.z, m);
            plo.w += __shfl_xor_sync(0xffffffffu, plo.w, m);
            phi.x += __shfl_xor_sync(0xffffffffu, phi.x, m);
            phi.y += __shfl_xor_sync(0xffffffffu, phi.y, m);
            phi.z += __shfl_xor_sync(0xffffffffu, phi.z, m);
            phi.w += __shfl_xor_sync(0xffffffffu, phi.w, m);
        }
        if (t == 0) {
            int r = m_base + mi * 16 + g;
            *(float4*)&part[((wid & 1) * BM + r) * 4] = plo;
            *(float4*)&part[((wid & 1) * BM + r + 8) * 4] = phi;
        }
    }
    __syncthreads();

    if (tid < BM) {
        int ge = tile0 + tid;
        float4 p0 = *(const float4*)&part[tid * 4];
        float4 p1 = *(const float4*)&part[(BM + tid) * 4];
        float4 o;
        o.x = p0.x + p1.x + b3s[0];
        o.y = p0.y + p1.y + b3s[1];
        o.z = p0.z + p1.z + b3s[2];
        o.w = p0.w + p1.w + b3s[3];
        if (ge < E) *(float4*)&out[ge * 4] = o;
    }
}

// ---------------------------------------------------------------------------
extern "C" void kernel_launch(void* const* d_in, const int* in_sizes, int n_in,
                              void* d_out, int out_size) {
    const float* x   = (const float*)d_in[0];
    const float* pos = (const float*)d_in[1];
    const int*   ei  = (const int*)  d_in[2];
    const float* Wa  = (const float*)d_in[3];
    const float* ba  = (const float*)d_in[4];
    const float* Wp  = (const float*)d_in[5];
    const float* bp  = (const float*)d_in[6];
    const float* W1  = (const float*)d_in[7];
    const float* b1  = (const float*)d_in[8];
    const float* W2  = (const float*)d_in[9];
    const float* b2  = (const float*)d_in[10];
    const float* W3  = (const float*)d_in[11];
    const float* b3  = (const float*)d_in[12];
    float* out = (float*)d_out;

    int N = in_sizes[0] / 16;
    int E = in_sizes[2] / 2;

    weight_prod<<<2, 128>>>(Wa, ba, Wp, bp, W1);
    prep_w2<<<4, 256>>>(W2);
    node_h_kernel<<<(N + NPB - 1) / NPB, 128>>>(x, pos, N);
    edge_mlp5<<<(E + BM - 1) / BM, THREADS>>>(
        pos, ei, W1, b1, b2, W3, b3, out, E);
}